// round 3
// baseline (speedup 1.0000x reference)
#include <cuda_runtime.h>
#include <math.h>
#include <stdint.h>

#define NN     50000
#define NE     800000
#define EF     16
#define HID    64
#define NC     10
#define NPICK  4096
#define NSCB   196            // ceil(NN/256)

typedef unsigned long long ull;

// ---------------- scratch (static device globals; no allocation) ----------------
__device__ float  g_M[4 * EF * HID];     // folded gate weights (prep output)
__device__ float  g_c[4 * HID];          // folded gate bias
__device__ float4 g_gate[NE];            // 4 per-layer gates, CSR-permuted order
__device__ float  g_deg[4 * NN];         // per-layer degree sums (atomic)
__device__ float  g_dis[4 * NN];         // rsqrt(deg+1)
__device__ __align__(256) float g_h[NN * HID];
__device__ __align__(256) float g_xa[NN * HID];
__device__ __align__(256) float g_xb[NN * HID];
__device__ int    g_cnt[NN];
__device__ int    g_tmp[NN];
__device__ int    g_bsum[256];
__device__ int    g_boff[256];
__device__ int    g_rowptr[NN + 1];
__device__ int    g_pos[NN];
__device__ int    g_perm[NE];            // edge id -> CSR slot
__device__ int    g_src[NE];             // CSR: source node per slot

// folded weights, uniform-address accessed -> constant path
__constant__ float c_M[4 * EF * HID];
__constant__ float c_c[4 * HID];
__constant__ float c_w2[4 * HID];
__constant__ float c_b2[4];

__device__ __forceinline__ int clampi(int v, int hi) {
    return v < 0 ? 0 : (v >= hi ? hi - 1 : v);
}
__device__ __forceinline__ ull pack2(float x) {
    ull r; unsigned int b = __float_as_uint(x);
    asm("mov.b64 %0, {%1, %2};" : "=l"(r) : "r"(b), "r"(b));
    return r;
}
__device__ __forceinline__ void fma2(ull& d, ull a, ull b) {
    asm("fma.rn.f32x2 %0, %1, %2, %0;" : "+l"(d) : "l"(a), "l"(b));
}
__device__ __forceinline__ void unpack2(ull v, float& lo, float& hi) {
    unsigned int l, h;
    asm("mov.b64 {%0, %1}, %2;" : "=r"(l), "=r"(h) : "l"(v));
    lo = __uint_as_float(l); hi = __uint_as_float(h);
}

// ---------------- weight folding: M_l = (encW1@encW2)@mlpW1_l ----------------
__global__ __launch_bounds__(256) void k_fold(
    const float* __restrict__ encW1, const float* __restrict__ encb1,
    const float* __restrict__ encW2, const float* __restrict__ encb2,
    const float* __restrict__ mlpW1, const float* __restrict__ mlpb1)
{
    __shared__ float sW1[256], sW2[256], sWc[256], sbc[16];
    int tid = threadIdx.x;
    sW1[tid] = encW1[tid];
    sW2[tid] = encW2[tid];
    __syncthreads();
    // Wc = W1 @ W2 (16x16)
    {
        int i = tid >> 4, j = tid & 15;
        float s = 0.f;
        #pragma unroll
        for (int k = 0; k < EF; k++) s += sW1[i * EF + k] * sW2[k * EF + j];
        sWc[tid] = s;
    }
    if (tid < EF) {
        float s = encb2[tid];
        #pragma unroll
        for (int k = 0; k < EF; k++) s += encb1[k] * sW2[k * EF + tid];
        sbc[tid] = s;
    }
    __syncthreads();
    // M[l][k][j] = sum_i Wc[k][i] * mlpW1[l][i][j]
    #pragma unroll 1
    for (int m = 0; m < 16; m++) {
        int idx = tid + 256 * m;                 // 0..4095
        int l = idx >> 10, k = (idx >> 6) & 15, j = idx & 63;
        float s = 0.f;
        #pragma unroll
        for (int i = 0; i < EF; i++) s += sWc[k * EF + i] * mlpW1[(l * EF + i) * HID + j];
        g_M[idx] = s;
    }
    // c[l][j] = sum_i bc[i]*mlpW1[l][i][j] + mlpb1[l][j]
    {
        int l = tid >> 6, j = tid & 63;
        float s = mlpb1[l * HID + j];
        #pragma unroll
        for (int i = 0; i < EF; i++) s += sbc[i] * mlpW1[(l * EF + i) * HID + j];
        g_c[tid] = s;
    }
}

// ---------------- zero counters ----------------
__global__ void k_zero() {
    int i = blockIdx.x * blockDim.x + threadIdx.x;
    if (i < 4 * NN) g_deg[i] = 0.f;
    if (i < NN) g_cnt[i] = 0;
}

// ---------------- CSR build ----------------
__global__ void k_count(const int* __restrict__ colp) {
    int e = blockIdx.x * blockDim.x + threadIdx.x;
    if (e < NE) atomicAdd(&g_cnt[clampi(colp[e], NN)], 1);
}

__global__ void k_scan1() {
    __shared__ int sh[256];
    int tid = threadIdx.x;
    int i = blockIdx.x * 256 + tid;
    int v = (i < NN) ? g_cnt[i] : 0;
    sh[tid] = v; __syncthreads();
    #pragma unroll
    for (int off = 1; off < 256; off <<= 1) {
        int t = (tid >= off) ? sh[tid - off] : 0;
        __syncthreads();
        sh[tid] += t;
        __syncthreads();
    }
    if (i < NN) g_tmp[i] = sh[tid] - v;          // exclusive in-block
    if (tid == 255) g_bsum[blockIdx.x] = sh[255];
}

__global__ void k_scan2() {
    __shared__ int sh[256];
    int tid = threadIdx.x;
    int v = (tid < NSCB) ? g_bsum[tid] : 0;
    sh[tid] = v; __syncthreads();
    #pragma unroll
    for (int off = 1; off < 256; off <<= 1) {
        int t = (tid >= off) ? sh[tid - off] : 0;
        __syncthreads();
        sh[tid] += t;
        __syncthreads();
    }
    g_boff[tid] = sh[tid] - v;                   // exclusive
}

__global__ void k_scan3() {
    int i = blockIdx.x * 256 + threadIdx.x;
    if (i < NN) {
        int r = g_tmp[i] + g_boff[blockIdx.x];
        g_rowptr[i] = r;
        g_pos[i] = r;
    }
    if (i == 0) g_rowptr[NN] = NE;
}

__global__ void k_scatter(const int* __restrict__ rowp,
                          const int* __restrict__ colp) {
    int e = blockIdx.x * blockDim.x + threadIdx.x;
    if (e >= NE) return;
    int c = clampi(colp[e], NN);
    int p = atomicAdd(&g_pos[c], 1);
    p = clampi(p, NE);
    g_src[p] = clampi(rowp[e], NN);
    g_perm[e] = p;
}

// ---------------- fused 4x gating MLP (folded weights, f32x2) ----------------
__global__ __launch_bounds__(256) void k_edge(const float* __restrict__ eattr,
                                              const int* __restrict__ colp)
{
    int e = blockIdx.x * 256 + threadIdx.x;
    if (e >= NE) return;

    float a[EF];
    const float4* a4 = (const float4*)(eattr + (size_t)e * EF);
    #pragma unroll
    for (int i = 0; i < 4; i++) {
        float4 v = a4[i];
        a[4*i] = v.x; a[4*i+1] = v.y; a[4*i+2] = v.z; a[4*i+3] = v.w;
    }
    int c = clampi(colp[e], NN);
    int p = g_perm[e];

    float gates[4];
    #pragma unroll 1
    for (int l = 0; l < 4; l++) {
        ull hv[32];
        const ull* cc = (const ull*)&c_c[l * HID];
        #pragma unroll
        for (int j = 0; j < 32; j++) hv[j] = cc[j];
        #pragma unroll
        for (int k = 0; k < EF; k++) {
            ull ak = pack2(a[k]);
            const ull* w = (const ull*)&c_M[(l * EF + k) * HID];
            #pragma unroll
            for (int j = 0; j < 32; j++) fma2(hv[j], ak, w[j]);
        }
        float z = c_b2[l];
        #pragma unroll
        for (int j = 0; j < 32; j++) {
            float lo, hi; unpack2(hv[j], lo, hi);
            z += fmaxf(lo, 0.f) * c_w2[l * HID + 2*j]
               + fmaxf(hi, 0.f) * c_w2[l * HID + 2*j + 1];
        }
        float g = 1.f / (1.f + __expf(-z));
        gates[l] = g;
        atomicAdd(&g_deg[l * NN + c], g);
    }
    g_gate[p] = make_float4(gates[0], gates[1], gates[2], gates[3]);
}

// ---------------- elementwise dis = rsqrt(deg + 1) ----------------
__global__ void k_disE() {
    int i = blockIdx.x * blockDim.x + threadIdx.x;
    if (i < 4 * NN) g_dis[i] = rsqrtf(g_deg[i] + 1.f);
}

// ---------------- h = x @ W (64x64), warp per row, f32x2 ----------------
__global__ __launch_bounds__(256) void k_gemm(const float* __restrict__ xin,
                                              const float* __restrict__ W) {
    __shared__ __align__(16) float sWf[HID * HID];
    for (int i = threadIdx.x; i < HID * HID; i += 256) sWf[i] = W[i];
    __syncthreads();
    int w = (blockIdx.x * 256 + threadIdx.x) >> 5;
    int lane = threadIdx.x & 31;
    if (w >= NN) return;
    float2 xv = *(const float2*)&xin[(size_t)w * HID + lane * 2];
    const ull* sW = (const ull*)sWf;
    ull acc = 0;
    #pragma unroll
    for (int k = 0; k < HID; k++) {
        float xk = __shfl_sync(0xffffffffu, (k & 1) ? xv.y : xv.x, k >> 1);
        fma2(acc, pack2(xk), sW[k * 32 + lane]);
    }
    float lo, hi; unpack2(acc, lo, hi);
    *(float2*)&g_h[(size_t)w * HID + lane * 2] = make_float2(lo, hi);
}

// ---------------- SpMM: out[c] = sum norm*h[src] + dis^2 h[c] + b ----------------
__global__ __launch_bounds__(256) void k_spmm(const float* __restrict__ dis4,
                                              const float* __restrict__ bias,
                                              float* __restrict__ xout,
                                              int l, int dorelu) {
    int c = (blockIdx.x * blockDim.x + threadIdx.x) >> 5;
    int lane = threadIdx.x & 31;
    if (c >= NN) return;
    int rs = g_rowptr[c], re = g_rowptr[c + 1];
    float disc = dis4[c];
    ull acc = 0;
    #pragma unroll 2
    for (int p = rs; p < re; p++) {
        int s = g_src[p];
        float ew = ((const float*)&g_gate[p])[l];
        float nrm = disc * ew * dis4[s];
        ull hvp = *(const ull*)&g_h[(size_t)s * HID + lane * 2];
        fma2(acc, pack2(nrm), hvp);
    }
    {   // self loop
        float ns = disc * disc;
        ull hvp = *(const ull*)&g_h[(size_t)c * HID + lane * 2];
        fma2(acc, pack2(ns), hvp);
    }
    float lo, hi; unpack2(acc, lo, hi);
    float2 b = *(const float2*)&bias[lane * 2];
    lo += b.x; hi += b.y;
    if (dorelu) { lo = fmaxf(lo, 0.f); hi = fmaxf(hi, 0.f); }
    *(float2*)&xout[(size_t)c * HID + lane * 2] = make_float2(lo, hi);
}

// ---------------- classifier + softmax at picked nodes ----------------
__global__ __launch_bounds__(128) void k_final(const float* __restrict__ xin,
                                               const float* __restrict__ linW,
                                               const float* __restrict__ linb,
                                               const int* __restrict__ pick,
                                               float* __restrict__ out) {
    __shared__ float sW[HID * NC];
    __shared__ float sb[NC];
    for (int i = threadIdx.x; i < HID * NC; i += 128) sW[i] = linW[i];
    if (threadIdx.x < NC) sb[threadIdx.x] = linb[threadIdx.x];
    __syncthreads();
    int t = blockIdx.x * 128 + threadIdx.x;
    if (t >= NPICK) return;
    int node = clampi(pick[t], NN);
    float lg[NC];
    #pragma unroll
    for (int j = 0; j < NC; j++) lg[j] = sb[j];
    const float4* xr = (const float4*)&xin[(size_t)node * HID];
    #pragma unroll
    for (int k4 = 0; k4 < 16; k4++) {
        float4 v = xr[k4];
        float xs[4] = {v.x, v.y, v.z, v.w};
        #pragma unroll
        for (int q = 0; q < 4; q++) {
            #pragma unroll
            for (int j = 0; j < NC; j++) lg[j] += xs[q] * sW[(k4 * 4 + q) * NC + j];
        }
    }
    float m = lg[0];
    #pragma unroll
    for (int j = 1; j < NC; j++) m = fmaxf(m, lg[j]);
    float ex[NC], s = 0.f;
    #pragma unroll
    for (int j = 0; j < NC; j++) { ex[j] = __expf(lg[j] - m); s += ex[j]; }
    float inv = 1.f / s;
    #pragma unroll
    for (int j = 0; j < NC; j++) out[(size_t)t * NC + j] = ex[j] * inv;
}

// ---------------- launch ----------------
extern "C" void kernel_launch(void* const* d_in, const int* in_sizes, int n_in,
                              void* d_out, int out_size) {
    const float* x      = (const float*)d_in[0];
    const float* eattr  = (const float*)d_in[1];
    const float* encW1  = (const float*)d_in[2];
    const float* encb1  = (const float*)d_in[3];
    const float* encW2  = (const float*)d_in[4];
    const float* encb2  = (const float*)d_in[5];
    const float* convW  = (const float*)d_in[6];
    const float* convB  = (const float*)d_in[7];
    const float* mlpW1  = (const float*)d_in[8];
    const float* mlpb1  = (const float*)d_in[9];
    const float* mlpW2  = (const float*)d_in[10];
    const float* mlpb2  = (const float*)d_in[11];
    const float* linW   = (const float*)d_in[12];
    const float* linb   = (const float*)d_in[13];
    const int* eidx     = (const int*)d_in[14];   // int32 (JAX x64 disabled)
    const int* pick     = (const int*)d_in[15];
    float* out = (float*)d_out;

    const int* rowp = eidx;
    const int* colp = eidx + NE;

    float *pM, *pC, *xa, *xb, *dis;
    cudaGetSymbolAddress((void**)&pM, g_M);
    cudaGetSymbolAddress((void**)&pC, g_c);
    cudaGetSymbolAddress((void**)&xa, g_xa);
    cudaGetSymbolAddress((void**)&xb, g_xb);
    cudaGetSymbolAddress((void**)&dis, g_dis);

    const int EB = (NE + 255) / 256;        // 3125
    const int WB = (NN * 32 + 255) / 256;   // 6250

    // fold weights, stage into __constant__
    k_fold<<<1, 256>>>(encW1, encb1, encW2, encb2, mlpW1, mlpb1);
    cudaMemcpyToSymbolAsync(c_M, pM, 4 * EF * HID * sizeof(float), 0, cudaMemcpyDeviceToDevice);
    cudaMemcpyToSymbolAsync(c_c, pC, 4 * HID * sizeof(float), 0, cudaMemcpyDeviceToDevice);
    cudaMemcpyToSymbolAsync(c_w2, mlpW2, 4 * HID * sizeof(float), 0, cudaMemcpyDeviceToDevice);
    cudaMemcpyToSymbolAsync(c_b2, mlpb2, 4 * sizeof(float), 0, cudaMemcpyDeviceToDevice);

    // CSR by destination (fast multi-block scan)
    k_zero<<<(4 * NN + 255) / 256, 256>>>();
    k_count<<<EB, 256>>>(colp);
    k_scan1<<<NSCB, 256>>>();
    k_scan2<<<1, 256>>>();
    k_scan3<<<NSCB, 256>>>();
    k_scatter<<<EB, 256>>>(rowp, colp);

    // gates + degrees in one pass
    k_edge<<<EB, 256>>>(eattr, colp);
    k_disE<<<(4 * NN + 255) / 256, 256>>>();

    const float* xin = x;
    float* bufs[2] = { xa, xb };
    for (int l = 0; l < 4; l++) {
        k_gemm<<<WB, 256>>>(xin, convW + l * HID * HID);
        k_spmm<<<WB, 256>>>(dis + l * NN, convB + l * HID, bufs[l & 1], l, (l < 3) ? 1 : 0);
        xin = bufs[l & 1];
    }

    k_final<<<32, 128>>>(xin, linW, linb, pick, out);
}

// round 4
// speedup vs baseline: 4.1797x; 4.1797x over previous
#include <cuda_runtime.h>
#include <math.h>
#include <stdint.h>

#define NN     50000
#define NE     800000
#define EF     16
#define HID    64
#define NC     10
#define NPICK  4096
#define NSCB   196            // ceil(NN/256)

typedef unsigned long long ull;

// ---------------- scratch (static device globals; no allocation) ----------------
__device__ float  g_M[4 * EF * HID];     // folded gate weights (prep output)
__device__ float  g_c[4 * HID];          // folded gate bias
__device__ float4 g_gate[NE];            // 4 per-layer gates, CSR-permuted order
__device__ float  g_deg[4 * NN];         // per-layer degree sums (atomic)
__device__ float  g_dis[4 * NN];         // rsqrt(deg+1)
__device__ __align__(256) float g_h[NN * HID];    // h' = dis * (x @ W)
__device__ __align__(256) float g_xa[NN * HID];
__device__ __align__(256) float g_xb[NN * HID];
__device__ int    g_cnt[NN];
__device__ int    g_tmp[NN];
__device__ int    g_bsum[256];
__device__ int    g_boff[256];
__device__ int    g_rowptr[NN + 1];
__device__ int    g_pos[NN];
__device__ int    g_perm[NE];            // edge id -> CSR slot
__device__ int    g_src[NE];             // CSR: source node per slot

__device__ __forceinline__ int clampi(int v, int hi) {
    return v < 0 ? 0 : (v >= hi ? hi - 1 : v);
}
__device__ __forceinline__ ull pack2(float x) {
    ull r; unsigned int b = __float_as_uint(x);
    asm("mov.b64 %0, {%1, %2};" : "=l"(r) : "r"(b), "r"(b));
    return r;
}
__device__ __forceinline__ void fma2(ull& d, ull a, ull b) {
    asm("fma.rn.f32x2 %0, %1, %2, %0;" : "+l"(d) : "l"(a), "l"(b));
}
__device__ __forceinline__ void unpack2(ull v, float& lo, float& hi) {
    unsigned int l, h;
    asm("mov.b64 {%0, %1}, %2;" : "=r"(l), "=r"(h) : "l"(v));
    lo = __uint_as_float(l); hi = __uint_as_float(h);
}

// ---------------- weight folding: M_l = (encW1@encW2)@mlpW1_l ----------------
__global__ __launch_bounds__(256) void k_fold(
    const float* __restrict__ encW1, const float* __restrict__ encb1,
    const float* __restrict__ encW2, const float* __restrict__ encb2,
    const float* __restrict__ mlpW1, const float* __restrict__ mlpb1)
{
    __shared__ float sW1[256], sW2[256], sWc[256], sbc[16];
    int tid = threadIdx.x;
    sW1[tid] = encW1[tid];
    sW2[tid] = encW2[tid];
    __syncthreads();
    {   // Wc = W1 @ W2 (16x16)
        int i = tid >> 4, j = tid & 15;
        float s = 0.f;
        #pragma unroll
        for (int k = 0; k < EF; k++) s += sW1[i * EF + k] * sW2[k * EF + j];
        sWc[tid] = s;
    }
    if (tid < EF) {
        float s = encb2[tid];
        #pragma unroll
        for (int k = 0; k < EF; k++) s += encb1[k] * sW2[k * EF + tid];
        sbc[tid] = s;
    }
    __syncthreads();
    #pragma unroll 1
    for (int m = 0; m < 16; m++) {
        int idx = tid + 256 * m;                 // 0..4095
        int l = idx >> 10, k = (idx >> 6) & 15, j = idx & 63;
        float s = 0.f;
        #pragma unroll
        for (int i = 0; i < EF; i++) s += sWc[k * EF + i] * mlpW1[(l * EF + i) * HID + j];
        g_M[idx] = s;
    }
    {
        int l = tid >> 6, j = tid & 63;
        float s = mlpb1[l * HID + j];
        #pragma unroll
        for (int i = 0; i < EF; i++) s += sbc[i] * mlpW1[(l * EF + i) * HID + j];
        g_c[tid] = s;
    }
}

// ---------------- zero counters ----------------
__global__ void k_zero() {
    int i = blockIdx.x * blockDim.x + threadIdx.x;
    if (i < 4 * NN) g_deg[i] = 0.f;
    if (i < NN) g_cnt[i] = 0;
}

// ---------------- CSR build ----------------
__global__ void k_count(const int* __restrict__ colp) {
    int e = blockIdx.x * blockDim.x + threadIdx.x;
    if (e < NE) atomicAdd(&g_cnt[clampi(colp[e], NN)], 1);
}

__global__ void k_scan1() {
    __shared__ int sh[256];
    int tid = threadIdx.x;
    int i = blockIdx.x * 256 + tid;
    int v = (i < NN) ? g_cnt[i] : 0;
    sh[tid] = v; __syncthreads();
    #pragma unroll
    for (int off = 1; off < 256; off <<= 1) {
        int t = (tid >= off) ? sh[tid - off] : 0;
        __syncthreads();
        sh[tid] += t;
        __syncthreads();
    }
    if (i < NN) g_tmp[i] = sh[tid] - v;          // exclusive in-block
    if (tid == 255) g_bsum[blockIdx.x] = sh[255];
}

__global__ void k_scan2() {
    __shared__ int sh[256];
    int tid = threadIdx.x;
    int v = (tid < NSCB) ? g_bsum[tid] : 0;
    sh[tid] = v; __syncthreads();
    #pragma unroll
    for (int off = 1; off < 256; off <<= 1) {
        int t = (tid >= off) ? sh[tid - off] : 0;
        __syncthreads();
        sh[tid] += t;
        __syncthreads();
    }
    g_boff[tid] = sh[tid] - v;                   // exclusive
}

__global__ void k_scan3() {
    int i = blockIdx.x * 256 + threadIdx.x;
    if (i < NN) {
        int r = g_tmp[i] + g_boff[blockIdx.x];
        g_rowptr[i] = r;
        g_pos[i] = r;
    }
    if (i == 0) g_rowptr[NN] = NE;
}

__global__ void k_scatter(const int* __restrict__ rowp,
                          const int* __restrict__ colp) {
    int e = blockIdx.x * blockDim.x + threadIdx.x;
    if (e >= NE) return;
    int c = clampi(colp[e], NN);
    int p = atomicAdd(&g_pos[c], 1);
    p = clampi(p, NE);
    g_src[p] = clampi(rowp[e], NN);
    g_perm[e] = p;
}

// ---------------- fused 4x gating MLP (folded weights in SHARED, f32x2) ----------------
__global__ __launch_bounds__(256) void k_edge(const float* __restrict__ eattr,
                                              const int* __restrict__ colp,
                                              const float* __restrict__ mlpW2,
                                              const float* __restrict__ mlpb2)
{
    __shared__ __align__(16) float sM[4 * EF * HID];   // 16 KB
    __shared__ __align__(16) float sC[4 * HID];
    __shared__ float sW2[4 * HID];
    __shared__ float sB2[4];
    int tid = threadIdx.x;
    for (int i = tid; i < 4 * EF * HID; i += 256) sM[i] = g_M[i];
    for (int i = tid; i < 4 * HID; i += 256) { sC[i] = g_c[i]; sW2[i] = mlpW2[i]; }
    if (tid < 4) sB2[tid] = mlpb2[tid];
    __syncthreads();

    int e = blockIdx.x * 256 + tid;
    if (e >= NE) return;

    float a[EF];
    const float4* a4 = (const float4*)(eattr + (size_t)e * EF);
    #pragma unroll
    for (int i = 0; i < 4; i++) {
        float4 v = a4[i];
        a[4*i] = v.x; a[4*i+1] = v.y; a[4*i+2] = v.z; a[4*i+3] = v.w;
    }
    int c = clampi(colp[e], NN);
    int p = g_perm[e];

    float gates[4];
    #pragma unroll 1
    for (int l = 0; l < 4; l++) {
        ull hv[32];
        {
            const float4* cc = (const float4*)&sC[l * HID];
            #pragma unroll
            for (int j = 0; j < 16; j++) {
                float4 v = cc[j];
                ull u0; asm("mov.b64 %0, {%1, %2};" : "=l"(u0) : "r"(__float_as_uint(v.x)), "r"(__float_as_uint(v.y)));
                ull u1; asm("mov.b64 %0, {%1, %2};" : "=l"(u1) : "r"(__float_as_uint(v.z)), "r"(__float_as_uint(v.w)));
                hv[2*j] = u0; hv[2*j+1] = u1;
            }
        }
        #pragma unroll
        for (int k = 0; k < EF; k++) {
            ull ak = pack2(a[k]);
            const float4* w4 = (const float4*)&sM[(l * EF + k) * HID];
            #pragma unroll
            for (int j = 0; j < 16; j++) {
                float4 v = w4[j];                 // one LDS.128 feeds two FFMA2
                ull w0; asm("mov.b64 %0, {%1, %2};" : "=l"(w0) : "r"(__float_as_uint(v.x)), "r"(__float_as_uint(v.y)));
                ull w1; asm("mov.b64 %0, {%1, %2};" : "=l"(w1) : "r"(__float_as_uint(v.z)), "r"(__float_as_uint(v.w)));
                fma2(hv[2*j], ak, w0);
                fma2(hv[2*j+1], ak, w1);
            }
        }
        float z = sB2[l];
        #pragma unroll
        for (int j = 0; j < 32; j++) {
            float lo, hi; unpack2(hv[j], lo, hi);
            z += fmaxf(lo, 0.f) * sW2[l * HID + 2*j]
               + fmaxf(hi, 0.f) * sW2[l * HID + 2*j + 1];
        }
        float g = 1.f / (1.f + __expf(-z));
        gates[l] = g;
        atomicAdd(&g_deg[l * NN + c], g);
    }
    g_gate[p] = make_float4(gates[0], gates[1], gates[2], gates[3]);
}

// ---------------- elementwise dis = rsqrt(deg + 1) ----------------
__global__ void k_disE() {
    int i = blockIdx.x * blockDim.x + threadIdx.x;
    if (i < 4 * NN) g_dis[i] = rsqrtf(g_deg[i] + 1.f);
}

// ---------------- h' = dis * (x @ W), warp per row, f32x2 ----------------
__global__ __launch_bounds__(256) void k_gemm(const float* __restrict__ xin,
                                              const float* __restrict__ W,
                                              const float* __restrict__ disl) {
    __shared__ __align__(16) float sWf[HID * HID];
    for (int i = threadIdx.x; i < HID * HID; i += 256) sWf[i] = W[i];
    __syncthreads();
    int w = (blockIdx.x * 256 + threadIdx.x) >> 5;
    int lane = threadIdx.x & 31;
    if (w >= NN) return;
    float2 xv = *(const float2*)&xin[(size_t)w * HID + lane * 2];
    const ull* sW = (const ull*)sWf;
    ull acc = 0;
    #pragma unroll
    for (int k = 0; k < HID; k++) {
        float xk = __shfl_sync(0xffffffffu, (k & 1) ? xv.y : xv.x, k >> 1);
        fma2(acc, pack2(xk), sW[k * 32 + lane]);
    }
    float d = disl[w];
    float lo, hi; unpack2(acc, lo, hi);
    *(float2*)&g_h[(size_t)w * HID + lane * 2] = make_float2(lo * d, hi * d);
}

// ---------------- SpMM: out[c] = disc*(sum ew*h'[src] + h'[c]) + b ----------------
__global__ __launch_bounds__(256) void k_spmm(const float* __restrict__ dis4,
                                              const float* __restrict__ bias,
                                              float* __restrict__ xout,
                                              int l, int dorelu) {
    int c = (blockIdx.x * blockDim.x + threadIdx.x) >> 5;
    int lane = threadIdx.x & 31;
    if (c >= NN) return;
    int rs = g_rowptr[c], re = g_rowptr[c + 1];
    ull acc = 0;
    #pragma unroll 4
    for (int p = rs; p < re; p++) {
        int s = g_src[p];
        float ew = ((const float*)&g_gate[p])[l];
        ull hvp = *(const ull*)&g_h[(size_t)s * HID + lane * 2];
        fma2(acc, pack2(ew), hvp);
    }
    {   // self loop: + h'[c]
        ull hvp = *(const ull*)&g_h[(size_t)c * HID + lane * 2];
        fma2(acc, pack2(1.f), hvp);
    }
    float disc = dis4[c];
    float lo, hi; unpack2(acc, lo, hi);
    float2 b = *(const float2*)&bias[lane * 2];
    lo = lo * disc + b.x; hi = hi * disc + b.y;
    if (dorelu) { lo = fmaxf(lo, 0.f); hi = fmaxf(hi, 0.f); }
    *(float2*)&xout[(size_t)c * HID + lane * 2] = make_float2(lo, hi);
}

// ---------------- classifier + softmax at picked nodes ----------------
__global__ __launch_bounds__(128) void k_final(const float* __restrict__ xin,
                                               const float* __restrict__ linW,
                                               const float* __restrict__ linb,
                                               const int* __restrict__ pick,
                                               float* __restrict__ out) {
    __shared__ float sW[HID * NC];
    __shared__ float sb[NC];
    for (int i = threadIdx.x; i < HID * NC; i += 128) sW[i] = linW[i];
    if (threadIdx.x < NC) sb[threadIdx.x] = linb[threadIdx.x];
    __syncthreads();
    int t = blockIdx.x * 128 + threadIdx.x;
    if (t >= NPICK) return;
    int node = clampi(pick[t], NN);
    float lg[NC];
    #pragma unroll
    for (int j = 0; j < NC; j++) lg[j] = sb[j];
    const float4* xr = (const float4*)&xin[(size_t)node * HID];
    #pragma unroll
    for (int k4 = 0; k4 < 16; k4++) {
        float4 v = xr[k4];
        float xs[4] = {v.x, v.y, v.z, v.w};
        #pragma unroll
        for (int q = 0; q < 4; q++) {
            #pragma unroll
            for (int j = 0; j < NC; j++) lg[j] += xs[q] * sW[(k4 * 4 + q) * NC + j];
        }
    }
    float m = lg[0];
    #pragma unroll
    for (int j = 1; j < NC; j++) m = fmaxf(m, lg[j]);
    float ex[NC], s = 0.f;
    #pragma unroll
    for (int j = 0; j < NC; j++) { ex[j] = __expf(lg[j] - m); s += ex[j]; }
    float inv = 1.f / s;
    #pragma unroll
    for (int j = 0; j < NC; j++) out[(size_t)t * NC + j] = ex[j] * inv;
}

// ---------------- launch ----------------
extern "C" void kernel_launch(void* const* d_in, const int* in_sizes, int n_in,
                              void* d_out, int out_size) {
    const float* x      = (const float*)d_in[0];
    const float* eattr  = (const float*)d_in[1];
    const float* encW1  = (const float*)d_in[2];
    const float* encb1  = (const float*)d_in[3];
    const float* encW2  = (const float*)d_in[4];
    const float* encb2  = (const float*)d_in[5];
    const float* convW  = (const float*)d_in[6];
    const float* convB  = (const float*)d_in[7];
    const float* mlpW1  = (const float*)d_in[8];
    const float* mlpb1  = (const float*)d_in[9];
    const float* mlpW2  = (const float*)d_in[10];
    const float* mlpb2  = (const float*)d_in[11];
    const float* linW   = (const float*)d_in[12];
    const float* linb   = (const float*)d_in[13];
    const int* eidx     = (const int*)d_in[14];   // int32 (JAX x64 disabled)
    const int* pick     = (const int*)d_in[15];
    float* out = (float*)d_out;

    const int* rowp = eidx;
    const int* colp = eidx + NE;

    float *xa, *xb, *dis;
    cudaGetSymbolAddress((void**)&xa, g_xa);
    cudaGetSymbolAddress((void**)&xb, g_xb);
    cudaGetSymbolAddress((void**)&dis, g_dis);

    const int EB = (NE + 255) / 256;        // 3125
    const int WB = (NN * 32 + 255) / 256;   // 6250

    // fold weights (tiny)
    k_fold<<<1, 256>>>(encW1, encb1, encW2, encb2, mlpW1, mlpb1);

    // CSR by destination (fast multi-block scan)
    k_zero<<<(4 * NN + 255) / 256, 256>>>();
    k_count<<<EB, 256>>>(colp);
    k_scan1<<<NSCB, 256>>>();
    k_scan2<<<1, 256>>>();
    k_scan3<<<NSCB, 256>>>();
    k_scatter<<<EB, 256>>>(rowp, colp);

    // gates + degrees in one pass
    k_edge<<<EB, 256>>>(eattr, colp, mlpW2, mlpb2);
    k_disE<<<(4 * NN + 255) / 256, 256>>>();

    const float* xin = x;
    float* bufs[2] = { xa, xb };
    for (int l = 0; l < 4; l++) {
        k_gemm<<<WB, 256>>>(xin, convW + l * HID * HID, dis + l * NN);
        k_spmm<<<WB, 256>>>(dis + l * NN, convB + l * HID, bufs[l & 1], l, (l < 3) ? 1 : 0);
        xin = bufs[l & 1];
    }

    k_final<<<32, 128>>>(xin, linW, linb, pick, out);
}

// round 5
// speedup vs baseline: 4.5911x; 1.0984x over previous
#include <cuda_runtime.h>
#include <math.h>
#include <stdint.h>

#define NN     50000
#define NE     800000
#define EF     16
#define HID    64
#define NC     10
#define NPICK  4096
#define NSCB   196            // ceil(NN/256)
#define EBLK   12500          // NE / 64

typedef unsigned long long ull;

// ---------------- scratch (static device globals; no allocation) ----------------
__device__ float  g_M[EF * 256];         // folded gate weights, [k][l*64+j]
__device__ float  g_c[256];              // folded gate bias, [l*64+j]
__device__ float4 g_gate[NE];            // 4 per-layer gates, CSR-permuted order
__device__ float  g_deg[4 * NN];         // per-layer degree sums (atomic)
__device__ __align__(256) float g_h[NN * HID];    // h' = dis * (x @ W)
__device__ __align__(256) float g_xa[NN * HID];
__device__ __align__(256) float g_xb[NN * HID];
__device__ int    g_cnt[NN];
__device__ int    g_tmp[NN];
__device__ int    g_bsum[256];
__device__ int    g_boff[256];
__device__ int    g_rowptr[NN + 1];
__device__ int    g_pos[NN];
__device__ int    g_perm[NE];            // edge id -> CSR slot
__device__ int    g_src[NE];             // CSR: source node per slot

__device__ __forceinline__ int clampi(int v, int hi) {
    return v < 0 ? 0 : (v >= hi ? hi - 1 : v);
}
__device__ __forceinline__ ull pack2(float x) {
    ull r; unsigned int b = __float_as_uint(x);
    asm("mov.b64 %0, {%1, %2};" : "=l"(r) : "r"(b), "r"(b));
    return r;
}
__device__ __forceinline__ void fma2(ull& d, ull a, ull b) {
    asm("fma.rn.f32x2 %0, %1, %2, %0;" : "+l"(d) : "l"(a), "l"(b));
}
__device__ __forceinline__ void unpack2(ull v, float& lo, float& hi) {
    unsigned int l, h;
    asm("mov.b64 {%0, %1}, %2;" : "=r"(l), "=r"(h) : "l"(v));
    lo = __uint_as_float(l); hi = __uint_as_float(h);
}

// ---------------- weight folding: M = (encW1@encW2)@mlpW1, [k][l*64+j] layout ----------------
__global__ __launch_bounds__(256) void k_fold(
    const float* __restrict__ encW1, const float* __restrict__ encb1,
    const float* __restrict__ encW2, const float* __restrict__ encb2,
    const float* __restrict__ mlpW1, const float* __restrict__ mlpb1)
{
    __shared__ float sW1[256], sW2[256], sWc[256], sbc[16];
    int tid = threadIdx.x;
    sW1[tid] = encW1[tid];
    sW2[tid] = encW2[tid];
    __syncthreads();
    {   // Wc = W1 @ W2 (16x16)
        int i = tid >> 4, j = tid & 15;
        float s = 0.f;
        #pragma unroll
        for (int k = 0; k < EF; k++) s += sW1[i * EF + k] * sW2[k * EF + j];
        sWc[tid] = s;
    }
    if (tid < EF) {
        float s = encb2[tid];
        #pragma unroll
        for (int k = 0; k < EF; k++) s += encb1[k] * sW2[k * EF + tid];
        sbc[tid] = s;
    }
    __syncthreads();
    #pragma unroll 1
    for (int m = 0; m < 16; m++) {
        int idx = tid + 256 * m;                 // 0..4095
        int l = idx >> 10, k = (idx >> 6) & 15, j = idx & 63;
        float s = 0.f;
        #pragma unroll
        for (int i = 0; i < EF; i++) s += sWc[k * EF + i] * mlpW1[(l * EF + i) * HID + j];
        g_M[k * 256 + l * 64 + j] = s;           // [k][n] layout, n = l*64+j
    }
    {
        int l = tid >> 6, j = tid & 63;
        float s = mlpb1[l * HID + j];
        #pragma unroll
        for (int i = 0; i < EF; i++) s += sbc[i] * mlpW1[(l * EF + i) * HID + j];
        g_c[tid] = s;                            // n = tid = l*64+j
    }
}

// ---------------- zero counters ----------------
__global__ void k_zero() {
    int i = blockIdx.x * blockDim.x + threadIdx.x;
    if (i < 4 * NN) g_deg[i] = 0.f;
    if (i < NN) g_cnt[i] = 0;
}

// ---------------- CSR build ----------------
__global__ void k_count(const int* __restrict__ colp) {
    int e = blockIdx.x * blockDim.x + threadIdx.x;
    if (e < NE) atomicAdd(&g_cnt[clampi(colp[e], NN)], 1);
}

__global__ void k_scan1() {
    __shared__ int sh[256];
    int tid = threadIdx.x;
    int i = blockIdx.x * 256 + tid;
    int v = (i < NN) ? g_cnt[i] : 0;
    sh[tid] = v; __syncthreads();
    #pragma unroll
    for (int off = 1; off < 256; off <<= 1) {
        int t = (tid >= off) ? sh[tid - off] : 0;
        __syncthreads();
        sh[tid] += t;
        __syncthreads();
    }
    if (i < NN) g_tmp[i] = sh[tid] - v;
    if (tid == 255) g_bsum[blockIdx.x] = sh[255];
}

__global__ void k_scan2() {
    __shared__ int sh[256];
    int tid = threadIdx.x;
    int v = (tid < NSCB) ? g_bsum[tid] : 0;
    sh[tid] = v; __syncthreads();
    #pragma unroll
    for (int off = 1; off < 256; off <<= 1) {
        int t = (tid >= off) ? sh[tid - off] : 0;
        __syncthreads();
        sh[tid] += t;
        __syncthreads();
    }
    g_boff[tid] = sh[tid] - v;
}

__global__ void k_scan3() {
    int i = blockIdx.x * 256 + threadIdx.x;
    if (i < NN) {
        int r = g_tmp[i] + g_boff[blockIdx.x];
        g_rowptr[i] = r;
        g_pos[i] = r;
    }
    if (i == 0) g_rowptr[NN] = NE;
}

__global__ void k_scatter(const int* __restrict__ rowp,
                          const int* __restrict__ colp) {
    int e = blockIdx.x * blockDim.x + threadIdx.x;
    if (e >= NE) return;
    int c = clampi(colp[e], NN);
    int p = atomicAdd(&g_pos[c], 1);
    p = clampi(p, NE);
    g_src[p] = clampi(rowp[e], NN);
    g_perm[e] = p;
}

// ---------------- tiled edge-gate GEMM: 64 edges x 256 outputs per block ----------------
// thread tile: 8 edges x 8 outputs (4 f32x2 pairs). eg = tid>>5 (8 edges), ng = tid&31 (n0 = 8*ng)
__global__ __launch_bounds__(256) void k_edge(const float* __restrict__ eattr,
                                              const int* __restrict__ colp,
                                              const float* __restrict__ mlpW2,
                                              const float* __restrict__ mlpb2)
{
    __shared__ __align__(16) float sA[EF][64];     // a-tile transposed: [k][edge]
    __shared__ __align__(16) float sW[EF][256];    // folded M: [k][n]
    __shared__ __align__(16) float sC[256];        // folded bias [n]
    __shared__ __align__(16) float sV[256];        // mlpW2 flattened [n]
    __shared__ float sB[4];

    int tid = threadIdx.x;
    // weights: straight 16 KB copy
    {
        const float4* src = (const float4*)g_M;
        float4* dst = (float4*)&sW[0][0];
        #pragma unroll
        for (int i = 0; i < 4; i++) dst[tid + 256 * i] = src[tid + 256 * i];
    }
    sC[tid] = g_c[tid];
    sV[tid] = mlpW2[tid];
    if (tid < 4) sB[tid] = mlpb2[tid];
    // a-tile: 64 rows x 16 floats; tid -> row = tid>>2, quad = tid&3; transpose into sA
    {
        int row = tid >> 2, q = tid & 3;
        float4 v = ((const float4*)(eattr + ((size_t)blockIdx.x * 64 + row) * EF))[q];
        sA[q * 4 + 0][row] = v.x;
        sA[q * 4 + 1][row] = v.y;
        sA[q * 4 + 2][row] = v.z;
        sA[q * 4 + 3][row] = v.w;
    }
    __syncthreads();

    const int eg = tid >> 5;        // edges 8*eg .. 8*eg+7
    const int ng = tid & 31;        // outputs n0 .. n0+7
    const int n0 = ng * 8;

    // acc[e][np]: f32x2 pair for outputs (n0+2np, n0+2np+1), init from bias
    ull acc[8][4];
    {
        const ull* cp = (const ull*)&sC[n0];
        ull c0 = cp[0], c1 = cp[1], c2 = cp[2], c3 = cp[3];
        #pragma unroll
        for (int e = 0; e < 8; e++) {
            acc[e][0] = c0; acc[e][1] = c1; acc[e][2] = c2; acc[e][3] = c3;
        }
    }

    #pragma unroll
    for (int k = 0; k < EF; k++) {
        const ull* wp = (const ull*)&sW[k][n0];         // 4 natural f32x2 pairs
        ull w0 = wp[0], w1 = wp[1], w2 = wp[2], w3 = wp[3];
        const float4* ap = (const float4*)&sA[k][eg * 8];
        float4 a0 = ap[0], a1 = ap[1];                  // 8 edge scalars (broadcast)
        float av[8] = {a0.x, a0.y, a0.z, a0.w, a1.x, a1.y, a1.z, a1.w};
        #pragma unroll
        for (int e = 0; e < 8; e++) {
            ull ae = pack2(av[e]);
            fma2(acc[e][0], ae, w0);
            fma2(acc[e][1], ae, w1);
            fma2(acc[e][2], ae, w2);
            fma2(acc[e][3], ae, w3);
        }
    }

    // epilogue: z partial = sum relu(h)*w2 over this thread's 8 outputs
    float w2v[8];
    #pragma unroll
    for (int i = 0; i < 8; i++) w2v[i] = sV[n0 + i];
    float pz[8];
    #pragma unroll
    for (int e = 0; e < 8; e++) {
        float s = 0.f;
        #pragma unroll
        for (int np = 0; np < 4; np++) {
            float lo, hi; unpack2(acc[e][np], lo, hi);
            s += fmaxf(lo, 0.f) * w2v[2 * np] + fmaxf(hi, 0.f) * w2v[2 * np + 1];
        }
        pz[e] = s;
    }
    // reduce across the 8 lanes sharing a layer (xor 1,2,4 stays in 8-lane group)
    #pragma unroll
    for (int off = 1; off < 8; off <<= 1) {
        #pragma unroll
        for (int e = 0; e < 8; e++)
            pz[e] += __shfl_xor_sync(0xffffffffu, pz[e], off);
    }
    if ((ng & 7) == 0) {
        int l = ng >> 3;                 // layer
        float bl = sB[l];
        #pragma unroll
        for (int e = 0; e < 8; e++) {
            int eglob = blockIdx.x * 64 + eg * 8 + e;
            float z = pz[e] + bl;
            float g = 1.f / (1.f + __expf(-z));
            int p = g_perm[eglob];
            int c = clampi(colp[eglob], NN);
            ((float*)&g_gate[p])[l] = g;
            atomicAdd(&g_deg[l * NN + c], g);
        }
    }
}

// ---------------- h' = rsqrt(deg+1) * (x @ W), warp per row, f32x2 ----------------
__global__ __launch_bounds__(256) void k_gemm(const float* __restrict__ xin,
                                              const float* __restrict__ W,
                                              const float* __restrict__ degl) {
    __shared__ __align__(16) float sWf[HID * HID];
    for (int i = threadIdx.x; i < HID * HID; i += 256) sWf[i] = W[i];
    __syncthreads();
    int w = (blockIdx.x * 256 + threadIdx.x) >> 5;
    int lane = threadIdx.x & 31;
    if (w >= NN) return;
    float2 xv = *(const float2*)&xin[(size_t)w * HID + lane * 2];
    const ull* sW = (const ull*)sWf;
    ull acc = 0;
    #pragma unroll
    for (int k = 0; k < HID; k++) {
        float xk = __shfl_sync(0xffffffffu, (k & 1) ? xv.y : xv.x, k >> 1);
        fma2(acc, pack2(xk), sW[k * 32 + lane]);
    }
    float d = rsqrtf(degl[w] + 1.f);
    float lo, hi; unpack2(acc, lo, hi);
    *(float2*)&g_h[(size_t)w * HID + lane * 2] = make_float2(lo * d, hi * d);
}

// ---------------- SpMM: out[c] = disc*(sum ew*h'[src] + h'[c]) + b ----------------
__global__ __launch_bounds__(256) void k_spmm(const float* __restrict__ degl,
                                              const float* __restrict__ bias,
                                              float* __restrict__ xout,
                                              int l, int dorelu) {
    int c = (blockIdx.x * blockDim.x + threadIdx.x) >> 5;
    int lane = threadIdx.x & 31;
    if (c >= NN) return;
    int rs = g_rowptr[c], re = g_rowptr[c + 1];
    ull acc = 0;
    #pragma unroll 4
    for (int p = rs; p < re; p++) {
        int s = g_src[p];
        float ew = ((const float*)&g_gate[p])[l];
        ull hvp = *(const ull*)&g_h[(size_t)s * HID + lane * 2];
        fma2(acc, pack2(ew), hvp);
    }
    {   // self loop: + h'[c]
        ull hvp = *(const ull*)&g_h[(size_t)c * HID + lane * 2];
        fma2(acc, pack2(1.f), hvp);
    }
    float disc = rsqrtf(degl[c] + 1.f);
    float lo, hi; unpack2(acc, lo, hi);
    float2 b = *(const float2*)&bias[lane * 2];
    lo = lo * disc + b.x; hi = hi * disc + b.y;
    if (dorelu) { lo = fmaxf(lo, 0.f); hi = fmaxf(hi, 0.f); }
    *(float2*)&xout[(size_t)c * HID + lane * 2] = make_float2(lo, hi);
}

// ---------------- classifier + softmax at picked nodes ----------------
__global__ __launch_bounds__(128) void k_final(const float* __restrict__ xin,
                                               const float* __restrict__ linW,
                                               const float* __restrict__ linb,
                                               const int* __restrict__ pick,
                                               float* __restrict__ out) {
    __shared__ float sW[HID * NC];
    __shared__ float sb[NC];
    for (int i = threadIdx.x; i < HID * NC; i += 128) sW[i] = linW[i];
    if (threadIdx.x < NC) sb[threadIdx.x] = linb[threadIdx.x];
    __syncthreads();
    int t = blockIdx.x * 128 + threadIdx.x;
    if (t >= NPICK) return;
    int node = clampi(pick[t], NN);
    float lg[NC];
    #pragma unroll
    for (int j = 0; j < NC; j++) lg[j] = sb[j];
    const float4* xr = (const float4*)&xin[(size_t)node * HID];
    #pragma unroll
    for (int k4 = 0; k4 < 16; k4++) {
        float4 v = xr[k4];
        float xs[4] = {v.x, v.y, v.z, v.w};
        #pragma unroll
        for (int q = 0; q < 4; q++) {
            #pragma unroll
            for (int j = 0; j < NC; j++) lg[j] += xs[q] * sW[(k4 * 4 + q) * NC + j];
        }
    }
    float m = lg[0];
    #pragma unroll
    for (int j = 1; j < NC; j++) m = fmaxf(m, lg[j]);
    float ex[NC], s = 0.f;
    #pragma unroll
    for (int j = 0; j < NC; j++) { ex[j] = __expf(lg[j] - m); s += ex[j]; }
    float inv = 1.f / s;
    #pragma unroll
    for (int j = 0; j < NC; j++) out[(size_t)t * NC + j] = ex[j] * inv;
}

// ---------------- launch ----------------
extern "C" void kernel_launch(void* const* d_in, const int* in_sizes, int n_in,
                              void* d_out, int out_size) {
    const float* x      = (const float*)d_in[0];
    const float* eattr  = (const float*)d_in[1];
    const float* encW1  = (const float*)d_in[2];
    const float* encb1  = (const float*)d_in[3];
    const float* encW2  = (const float*)d_in[4];
    const float* encb2  = (const float*)d_in[5];
    const float* convW  = (const float*)d_in[6];
    const float* convB  = (const float*)d_in[7];
    const float* mlpW1  = (const float*)d_in[8];
    const float* mlpb1  = (const float*)d_in[9];
    const float* mlpW2  = (const float*)d_in[10];
    const float* mlpb2  = (const float*)d_in[11];
    const float* linW   = (const float*)d_in[12];
    const float* linb   = (const float*)d_in[13];
    const int* eidx     = (const int*)d_in[14];   // int32 (JAX x64 disabled)
    const int* pick     = (const int*)d_in[15];
    float* out = (float*)d_out;

    const int* rowp = eidx;
    const int* colp = eidx + NE;

    float *xa, *xb, *deg;
    cudaGetSymbolAddress((void**)&xa, g_xa);
    cudaGetSymbolAddress((void**)&xb, g_xb);
    cudaGetSymbolAddress((void**)&deg, g_deg);

    const int EB = (NE + 255) / 256;        // 3125
    const int WB = (NN * 32 + 255) / 256;   // 6250

    // fold weights (tiny)
    k_fold<<<1, 256>>>(encW1, encb1, encW2, encb2, mlpW1, mlpb1);

    // CSR by destination (fast multi-block scan)
    k_zero<<<(4 * NN + 255) / 256, 256>>>();
    k_count<<<EB, 256>>>(colp);
    k_scan1<<<NSCB, 256>>>();
    k_scan2<<<1, 256>>>();
    k_scan3<<<NSCB, 256>>>();
    k_scatter<<<EB, 256>>>(rowp, colp);

    // gates + degrees in one tiled-GEMM pass
    k_edge<<<EBLK, 256>>>(eattr, colp, mlpW2, mlpb2);

    const float* xin = x;
    float* bufs[2] = { xa, xb };
    for (int l = 0; l < 4; l++) {
        k_gemm<<<WB, 256>>>(xin, convW + l * HID * HID, deg + l * NN);
        k_spmm<<<WB, 256>>>(deg + l * NN, convB + l * HID, bufs[l & 1], l, (l < 3) ? 1 : 0);
        xin = bufs[l & 1];
    }

    k_final<<<32, 128>>>(xin, linW, linb, pick, out);
}